// round 12
// baseline (speedup 1.0000x reference)
#include <cuda_runtime.h>
#include <cuda_fp16.h>
#include <math.h>
#include <stdint.h>

#define N_NODES 100000
#define D_FEAT  128
#define E_EDGES 600000
#define C_OUT   256

// ---------------- scratch (no allocs allowed; __device__ globals) -------------
__device__ __align__(16) float g_sums[(size_t)N_NODES * D_FEAT];   // 51.2 MB
__device__ float g_cnt[N_NODES];
__device__ int   g_idx64;
// W pre-transposed, fp16: [n][k] rows of 256 fp16 (512B)
__device__ __align__(16) unsigned char g_B16_t[256 * 512];

// ---------------- merged init: zero + W prep + idx-width detect ---------------
#define ZBLKS 12500
__global__ void init_kernel(const float* __restrict__ W,
                            const long long* __restrict__ ei) {
    if (blockIdx.x < ZBLKS) {
        int i = blockIdx.x * 256 + threadIdx.x;
        const int TOT4 = N_NODES * D_FEAT / 4;
        if (i < TOT4) reinterpret_cast<float4*>(g_sums)[i] = make_float4(0.f, 0.f, 0.f, 0.f);
        if (i < N_NODES) g_cnt[i] = 0.f;
    } else {
        int k = blockIdx.x - ZBLKS;      // 0..255
        int n = threadIdx.x;             // 0..255
        float w = W[k * C_OUT + n];
        reinterpret_cast<__half*>(g_B16_t)[n * 256 + k] = __float2half_rn(w);
        if (k == 0 && n == 0) {
            int ok = 1;
#pragma unroll
            for (int i = 0; i < 8; i++) {
                long long v = ei[i];
                if (v < 0 || v >= (long long)N_NODES) ok = 0;
            }
            g_idx64 = ok;
        }
    }
}

// ---------------- vector reduction helper ------------------------------------
__device__ __forceinline__ void red_add_v4(float* p, float4 v) {
    asm volatile("red.global.add.v4.f32 [%0], {%1, %2, %3, %4};"
                 :: "l"(p), "f"(v.x), "f"(v.y), "f"(v.z), "f"(v.w) : "memory");
}

// ---------------- edge scatter: 4 edges per warp (R8-best) --------------------
#define EPW 4
__global__ void scatter_kernel(const float* __restrict__ x,
                               const long long* __restrict__ ei) {
    const int warp = (blockIdx.x * blockDim.x + threadIdx.x) >> 5;
    const int lane = threadIdx.x & 31;
    const int e0 = warp * EPW;
    if (e0 >= E_EDGES) return;

    const int use64 = g_idx64;
    int r[EPW], c[EPW];
#pragma unroll
    for (int i = 0; i < EPW; i++) {
        int e = e0 + i;                      // E_EDGES % EPW == 0
        if (use64) {
            r[i] = (int)ei[e];
            c[i] = (int)ei[E_EDGES + e];
        } else {
            const int* p = (const int*)ei;
            r[i] = p[e];
            c[i] = p[E_EDGES + e];
        }
    }

    float4 v[EPW];
#pragma unroll
    for (int i = 0; i < EPW; i++)
        if (r[i] != c[i])
            v[i] = *reinterpret_cast<const float4*>(x + (size_t)c[i] * D_FEAT + lane * 4);

#pragma unroll
    for (int i = 0; i < EPW; i++) {
        if (r[i] != c[i]) {
            red_add_v4(g_sums + (size_t)r[i] * D_FEAT + lane * 4, v[i]);
            if (lane == 0) atomicAdd(&g_cnt[r[i]], 1.0f);
        }
    }
}

// ---------------- HMMA GEMM: (mean||x) @ W + bias + row-L2-normalize ---------
// BM=128, BN=256, 512 threads = 16 warps as 4(M)x4(N); warp tile 32x64.
// mma.sync m16n8k16 fp16->f32, SINGLE pass (A and B both plain fp16).
// Fragments loaded with ldmatrix.x4. smem rows padded to 272B: conflict-free.
#define BMROWS 128
#define ROWB 272
#define ROWH 136
#define SM_BIAS 0
#define SM_RED  1024
#define SM_A    4096
#define SM_B    (SM_A + BMROWS * ROWB)     // 38912
#define SM_TOT  (SM_B + 256 * ROWB)        // 108544

__device__ __forceinline__ void mma16816(float d[4], const uint32_t a[4], const uint32_t b[2]) {
    asm volatile("mma.sync.aligned.m16n8k16.row.col.f32.f16.f16.f32 "
                 "{%0,%1,%2,%3}, {%4,%5,%6,%7}, {%8,%9}, {%0,%1,%2,%3};"
                 : "+f"(d[0]), "+f"(d[1]), "+f"(d[2]), "+f"(d[3])
                 : "r"(a[0]), "r"(a[1]), "r"(a[2]), "r"(a[3]), "r"(b[0]), "r"(b[1]));
}

__device__ __forceinline__ void ldsm_x4(uint32_t r[4], uint32_t addr) {
    asm volatile("ldmatrix.sync.aligned.m8n8.x4.shared.b16 {%0,%1,%2,%3}, [%4];"
                 : "=r"(r[0]), "=r"(r[1]), "=r"(r[2]), "=r"(r[3]) : "r"(addr));
}

__global__ void __launch_bounds__(512, 1) gemm_hmma_kernel(const float* __restrict__ x,
                                                           const float* __restrict__ bias,
                                                           float* __restrict__ out) {
    extern __shared__ __align__(16) unsigned char smem[];
    const uint32_t smb = (uint32_t)__cvta_generic_to_shared(smem);
    const int tid = threadIdx.x;
    const int wid = tid >> 5;
    const int lid = tid & 31;
    const int wm  = wid >> 2;            // 0..3 : rows wm*32..+31
    const int wn  = wid & 3;             // 0..3 : cols wn*64..+63
    const int r4  = lid >> 2;            // 0..7
    const int c4  = lid & 3;             // 0..3
    const int node0 = blockIdx.x * BMROWS;

    // ldmatrix per-lane source rows/k-offsets
    const int a_lrow = (lid & 7) + ((lid & 8)  ? 8 : 0);
    const int a_lko  = (lid & 16) ? 8 : 0;
    const int b_lrow = (lid & 7) + ((lid & 16) ? 8 : 0);
    const int b_lko  = (lid & 8) ? 8 : 0;

    // stage bias
    if (tid < 256) reinterpret_cast<float*>(smem + SM_BIAS)[tid] = bias[tid];

    // A staging role: row = tid>>2 (0..127), k-base = (tid&3)*32 within 128-chunk
    const int arow = tid >> 2;
    const int akb  = (tid & 3) * 32;
    const int amg  = node0 + arow;
    const bool a_ok = (amg < N_NODES);
    const float inv_cnt = a_ok ? (1.0f / fmaxf(g_cnt[amg], 1.0f)) : 0.f;

    float acc[2][8][4];
#pragma unroll
    for (int mt = 0; mt < 2; mt++)
#pragma unroll
        for (int nt = 0; nt < 8; nt++)
#pragma unroll
            for (int q = 0; q < 4; q++) acc[mt][nt][q] = 0.f;

    const uint4* gb = reinterpret_cast<const uint4*>(g_B16_t);

#pragma unroll 1
    for (int c = 0; c < 2; c++) {
        // ---- stage A (plain fp16) ----
        {
            const float* asrc = (c == 0) ? (g_sums + (size_t)amg * D_FEAT + akb)
                                         : (x      + (size_t)amg * D_FEAT + akb);
            const float scale = (c == 0) ? inv_cnt : 1.0f;
#pragma unroll
            for (int q = 0; q < 8; q++) {
                float4 v = make_float4(0.f, 0.f, 0.f, 0.f);
                if (a_ok) {
                    v = *reinterpret_cast<const float4*>(asrc + q * 4);
                    v.x *= scale; v.y *= scale; v.z *= scale; v.w *= scale;
                }
                __half hx = __float2half_rn(v.x), hy = __float2half_rn(v.y);
                __half hz = __float2half_rn(v.z), hw = __float2half_rn(v.w);
                uint32_t hi0 = (uint32_t)__half_as_ushort(hx) | ((uint32_t)__half_as_ushort(hy) << 16);
                uint32_t hi1 = (uint32_t)__half_as_ushort(hz) | ((uint32_t)__half_as_ushort(hw) << 16);
                uint32_t byt = (uint32_t)(arow * ROWH + akb + q * 4) * 2;
                *reinterpret_cast<uint32_t*>(smem + SM_A + byt)     = hi0;
                *reinterpret_cast<uint32_t*>(smem + SM_A + byt + 4) = hi1;
            }
        }
        // ---- stage B (coalesced copy of 128-fp16 slices) ----
#pragma unroll
        for (int i = 0; i < 8; i++) {
            int f = i * 512 + tid;           // 0..4095
            int n = f >> 4;
            int j = f & 15;
            *reinterpret_cast<uint4*>(smem + SM_B + n * ROWB + j * 16) = gb[n * 32 + c * 16 + j];
        }
        __syncthreads();

        // ---- compute: 8 k-steps of 16 ----
#pragma unroll
        for (int ks = 0; ks < 8; ks++) {
            const int kb = ks * 16;
            uint32_t af[2][4];
#pragma unroll
            for (int mt = 0; mt < 2; mt++) {
                uint32_t ao = smb + (uint32_t)((wm * 32 + mt * 16 + a_lrow) * ROWH + kb + a_lko) * 2;
                ldsm_x4(af[mt], SM_A + ao);
            }
            uint32_t bf[4][4];
#pragma unroll
            for (int np = 0; np < 4; np++) {
                uint32_t bo = smb + (uint32_t)((wn * 64 + np * 16 + b_lrow) * ROWH + kb + b_lko) * 2;
                ldsm_x4(bf[np], SM_B + bo);
            }
            // single sweep of 16 independent mmas
#pragma unroll
            for (int mt = 0; mt < 2; mt++)
#pragma unroll
                for (int nt = 0; nt < 8; nt++)
                    mma16816(acc[mt][nt], af[mt], &bf[nt >> 1][(nt & 1) * 2]);
        }
        __syncthreads();
    }

    // ---- epilogue: + bias, row L2 norm, store ----
    const float* bsm = reinterpret_cast<const float*>(smem + SM_BIAS);
    float ssq[2][2] = {{0.f, 0.f}, {0.f, 0.f}};
#pragma unroll
    for (int mt = 0; mt < 2; mt++)
#pragma unroll
        for (int nt = 0; nt < 8; nt++) {
            int col = wn * 64 + nt * 8 + 2 * c4;
            float b0 = bsm[col], b1 = bsm[col + 1];
            float* d = acc[mt][nt];
            d[0] += b0; d[1] += b1; d[2] += b0; d[3] += b1;
            ssq[mt][0] += d[0] * d[0] + d[1] * d[1];
            ssq[mt][1] += d[2] * d[2] + d[3] * d[3];
        }
#pragma unroll
    for (int off = 1; off <= 2; off <<= 1) {
        ssq[0][0] += __shfl_xor_sync(0xFFFFFFFFu, ssq[0][0], off);
        ssq[0][1] += __shfl_xor_sync(0xFFFFFFFFu, ssq[0][1], off);
        ssq[1][0] += __shfl_xor_sync(0xFFFFFFFFu, ssq[1][0], off);
        ssq[1][1] += __shfl_xor_sync(0xFFFFFFFFu, ssq[1][1], off);
    }
    float* rp = reinterpret_cast<float*>(smem + SM_RED);   // [4 warps_n][128 rows]
    if (c4 == 0) {
#pragma unroll
        for (int mt = 0; mt < 2; mt++)
#pragma unroll
            for (int h = 0; h < 2; h++)
                rp[wn * BMROWS + wm * 32 + mt * 16 + r4 + 8 * h] = ssq[mt][h];
    }
    __syncthreads();

#pragma unroll
    for (int mt = 0; mt < 2; mt++)
#pragma unroll
        for (int h = 0; h < 2; h++) {
            int rr = wm * 32 + mt * 16 + r4 + 8 * h;
            float s = rp[rr] + rp[BMROWS + rr] + rp[2 * BMROWS + rr] + rp[3 * BMROWS + rr];
            float invn = 1.0f / fmaxf(sqrtf(s), 1e-12f);
            int row = node0 + rr;
            if (row < N_NODES) {
#pragma unroll
                for (int nt = 0; nt < 8; nt++) {
                    float* d = acc[mt][nt];
                    float2 o;
                    o.x = d[2 * h]     * invn;
                    o.y = d[2 * h + 1] * invn;
                    *reinterpret_cast<float2*>(out + (size_t)row * C_OUT + wn * 64 + nt * 8 + 2 * c4) = o;
                }
            }
        }
}

// ---------------- launch ------------------------------------------------------
extern "C" void kernel_launch(void* const* d_in, const int* in_sizes, int n_in,
                              void* d_out, int out_size) {
    const float*     x    = (const float*)d_in[0];      // [100000,128]
    const long long* ei   = (const long long*)d_in[1];  // [2,600000]
    const float*     W    = (const float*)d_in[2];      // [256,256]
    const float*     bias = (const float*)d_in[3];      // [1,256]
    float*           out  = (float*)d_out;              // [100000,256]

    init_kernel<<<ZBLKS + 256, 256>>>(W, ei);

    {
        long long threads = (long long)(E_EDGES / EPW) * 32;
        scatter_kernel<<<(int)((threads + 255) / 256), 256>>>(x, ei);
    }

    {
        cudaFuncSetAttribute(gemm_hmma_kernel, cudaFuncAttributeMaxDynamicSharedMemorySize, SM_TOT);
        int grid = (N_NODES + BMROWS - 1) / BMROWS;     // 782
        gemm_hmma_kernel<<<grid, 512, SM_TOT>>>(x, bias, out);
    }
}

// round 13
// speedup vs baseline: 1.7177x; 1.7177x over previous
#include <cuda_runtime.h>
#include <cuda_fp16.h>
#include <math.h>
#include <stdint.h>

#define N_NODES 100000
#define D_FEAT  128
#define E_EDGES 600000
#define C_OUT   256

// ---------------- scratch (no allocs allowed; __device__ globals) -------------
__device__ __align__(16) float g_sums[(size_t)N_NODES * D_FEAT];   // 51.2 MB
__device__ float g_cnt[N_NODES];
__device__ int   g_idx64;
// W pre-transposed, fp16: [n][k] rows of 256 fp16 (512B)
__device__ __align__(16) unsigned char g_B16_t[256 * 512];

// ---------------- merged init: zero + W prep + idx-width detect ---------------
#define ZBLKS 12500
__global__ void init_kernel(const float* __restrict__ W,
                            const long long* __restrict__ ei) {
    if (blockIdx.x < ZBLKS) {
        int i = blockIdx.x * 256 + threadIdx.x;
        const int TOT4 = N_NODES * D_FEAT / 4;
        if (i < TOT4) reinterpret_cast<float4*>(g_sums)[i] = make_float4(0.f, 0.f, 0.f, 0.f);
        if (i < N_NODES) g_cnt[i] = 0.f;
    } else {
        int k = blockIdx.x - ZBLKS;      // 0..255
        int n = threadIdx.x;             // 0..255
        float w = W[k * C_OUT + n];
        reinterpret_cast<__half*>(g_B16_t)[n * 256 + k] = __float2half_rn(w);
        if (k == 0 && n == 0) {
            int ok = 1;
#pragma unroll
            for (int i = 0; i < 8; i++) {
                long long v = ei[i];
                if (v < 0 || v >= (long long)N_NODES) ok = 0;
            }
            g_idx64 = ok;
        }
    }
}

// ---------------- vector reduction helper ------------------------------------
__device__ __forceinline__ void red_add_v4(float* p, float4 v) {
    asm volatile("red.global.add.v4.f32 [%0], {%1, %2, %3, %4};"
                 :: "l"(p), "f"(v.x), "f"(v.y), "f"(v.z), "f"(v.w) : "memory");
}

// ---------------- edge scatter: 4 edges per warp (R8-best) --------------------
#define EPW 4
__global__ void scatter_kernel(const float* __restrict__ x,
                               const long long* __restrict__ ei) {
    const int warp = (blockIdx.x * blockDim.x + threadIdx.x) >> 5;
    const int lane = threadIdx.x & 31;
    const int e0 = warp * EPW;
    if (e0 >= E_EDGES) return;

    const int use64 = g_idx64;
    int r[EPW], c[EPW];
#pragma unroll
    for (int i = 0; i < EPW; i++) {
        int e = e0 + i;                      // E_EDGES % EPW == 0
        if (use64) {
            r[i] = (int)ei[e];
            c[i] = (int)ei[E_EDGES + e];
        } else {
            const int* p = (const int*)ei;
            r[i] = p[e];
            c[i] = p[E_EDGES + e];
        }
    }

    float4 v[EPW];
#pragma unroll
    for (int i = 0; i < EPW; i++)
        if (r[i] != c[i])
            v[i] = *reinterpret_cast<const float4*>(x + (size_t)c[i] * D_FEAT + lane * 4);

#pragma unroll
    for (int i = 0; i < EPW; i++) {
        if (r[i] != c[i]) {
            red_add_v4(g_sums + (size_t)r[i] * D_FEAT + lane * 4, v[i]);
            if (lane == 0) atomicAdd(&g_cnt[r[i]], 1.0f);
        }
    }
}

// ---------------- HMMA GEMM: (mean||x) @ W + bias + row-L2-normalize ---------
// BM=128, BN=256, 512 threads = 16 warps as 4(M)x4(N); warp tile 32x64.
// mma.sync m16n8k16 fp16->f32, SINGLE pass (A and B both plain fp16).
// Fragments loaded with ldmatrix.x4. smem rows padded to 272B: conflict-free.
#define BMROWS 128
#define ROWB 272
#define ROWH 136
#define SM_BIAS 0
#define SM_RED  1024
#define SM_A    4096
#define SM_B    (SM_A + BMROWS * ROWB)     // 38912
#define SM_TOT  (SM_B + 256 * ROWB)        // 108544

__device__ __forceinline__ void mma16816(float d[4], const uint32_t a[4], const uint32_t b[2]) {
    asm volatile("mma.sync.aligned.m16n8k16.row.col.f32.f16.f16.f32 "
                 "{%0,%1,%2,%3}, {%4,%5,%6,%7}, {%8,%9}, {%0,%1,%2,%3};"
                 : "+f"(d[0]), "+f"(d[1]), "+f"(d[2]), "+f"(d[3])
                 : "r"(a[0]), "r"(a[1]), "r"(a[2]), "r"(a[3]), "r"(b[0]), "r"(b[1]));
}

__device__ __forceinline__ void ldsm_x4(uint32_t r[4], uint32_t addr) {
    asm volatile("ldmatrix.sync.aligned.m8n8.x4.shared.b16 {%0,%1,%2,%3}, [%4];"
                 : "=r"(r[0]), "=r"(r[1]), "=r"(r[2]), "=r"(r[3]) : "r"(addr));
}

__global__ void __launch_bounds__(512, 1) gemm_hmma_kernel(const float* __restrict__ x,
                                                           const float* __restrict__ bias,
                                                           float* __restrict__ out) {
    extern __shared__ __align__(16) unsigned char smem[];
    const uint32_t smb = (uint32_t)__cvta_generic_to_shared(smem);
    const int tid = threadIdx.x;
    const int wid = tid >> 5;
    const int lid = tid & 31;
    const int wm  = wid >> 2;            // 0..3 : rows wm*32..+31
    const int wn  = wid & 3;             // 0..3 : cols wn*64..+63
    const int r4  = lid >> 2;            // 0..7
    const int c4  = lid & 3;             // 0..3
    const int node0 = blockIdx.x * BMROWS;

    // ldmatrix per-lane source rows/k-offsets
    const int a_lrow = (lid & 7) + ((lid & 8)  ? 8 : 0);
    const int a_lko  = (lid & 16) ? 8 : 0;
    const int b_lrow = (lid & 7) + ((lid & 16) ? 8 : 0);
    const int b_lko  = (lid & 8) ? 8 : 0;

    // stage bias
    if (tid < 256) reinterpret_cast<float*>(smem + SM_BIAS)[tid] = bias[tid];

    // A staging role: row = tid>>2 (0..127), k-base = (tid&3)*32 within 128-chunk
    const int arow = tid >> 2;
    const int akb  = (tid & 3) * 32;
    const int amg  = node0 + arow;
    const bool a_ok = (amg < N_NODES);
    const float inv_cnt = a_ok ? (1.0f / fmaxf(g_cnt[amg], 1.0f)) : 0.f;

    float acc[2][8][4];
#pragma unroll
    for (int mt = 0; mt < 2; mt++)
#pragma unroll
        for (int nt = 0; nt < 8; nt++)
#pragma unroll
            for (int q = 0; q < 4; q++) acc[mt][nt][q] = 0.f;

    const uint4* gb = reinterpret_cast<const uint4*>(g_B16_t);

#pragma unroll 1
    for (int c = 0; c < 2; c++) {
        // ---- stage A (plain fp16) ----
        {
            const float* asrc = (c == 0) ? (g_sums + (size_t)amg * D_FEAT + akb)
                                         : (x      + (size_t)amg * D_FEAT + akb);
            const float scale = (c == 0) ? inv_cnt : 1.0f;
#pragma unroll
            for (int q = 0; q < 8; q++) {
                float4 v = make_float4(0.f, 0.f, 0.f, 0.f);
                if (a_ok) {
                    v = *reinterpret_cast<const float4*>(asrc + q * 4);
                    v.x *= scale; v.y *= scale; v.z *= scale; v.w *= scale;
                }
                __half hx = __float2half_rn(v.x), hy = __float2half_rn(v.y);
                __half hz = __float2half_rn(v.z), hw = __float2half_rn(v.w);
                uint32_t hi0 = (uint32_t)__half_as_ushort(hx) | ((uint32_t)__half_as_ushort(hy) << 16);
                uint32_t hi1 = (uint32_t)__half_as_ushort(hz) | ((uint32_t)__half_as_ushort(hw) << 16);
                uint32_t byt = (uint32_t)(arow * ROWH + akb + q * 4) * 2;
                *reinterpret_cast<uint32_t*>(smem + SM_A + byt)     = hi0;
                *reinterpret_cast<uint32_t*>(smem + SM_A + byt + 4) = hi1;
            }
        }
        // ---- stage B (coalesced copy of 128-fp16 slices) ----
#pragma unroll
        for (int i = 0; i < 8; i++) {
            int f = i * 512 + tid;           // 0..4095
            int n = f >> 4;
            int j = f & 15;
            *reinterpret_cast<uint4*>(smem + SM_B + n * ROWB + j * 16) = gb[n * 32 + c * 16 + j];
        }
        __syncthreads();

        // ---- compute: 8 k-steps of 16 ----
#pragma unroll
        for (int ks = 0; ks < 8; ks++) {
            const int kb = ks * 16;
            uint32_t af[2][4];
#pragma unroll
            for (int mt = 0; mt < 2; mt++) {
                uint32_t ao = smb + (uint32_t)((wm * 32 + mt * 16 + a_lrow) * ROWH + kb + a_lko) * 2;
                ldsm_x4(af[mt], SM_A + ao);
            }
            uint32_t bf[4][4];
#pragma unroll
            for (int np = 0; np < 4; np++) {
                uint32_t bo = smb + (uint32_t)((wn * 64 + np * 16 + b_lrow) * ROWH + kb + b_lko) * 2;
                ldsm_x4(bf[np], SM_B + bo);
            }
            // single sweep of 16 independent mmas
#pragma unroll
            for (int mt = 0; mt < 2; mt++)
#pragma unroll
                for (int nt = 0; nt < 8; nt++)
                    mma16816(acc[mt][nt], af[mt], &bf[nt >> 1][(nt & 1) * 2]);
        }
        __syncthreads();
    }

    // ---- epilogue: + bias, row L2 norm, store ----
    const float* bsm = reinterpret_cast<const float*>(smem + SM_BIAS);
    float ssq[2][2] = {{0.f, 0.f}, {0.f, 0.f}};
#pragma unroll
    for (int mt = 0; mt < 2; mt++)
#pragma unroll
        for (int nt = 0; nt < 8; nt++) {
            int col = wn * 64 + nt * 8 + 2 * c4;
            float b0 = bsm[col], b1 = bsm[col + 1];
            float* d = acc[mt][nt];
            d[0] += b0; d[1] += b1; d[2] += b0; d[3] += b1;
            ssq[mt][0] += d[0] * d[0] + d[1] * d[1];
            ssq[mt][1] += d[2] * d[2] + d[3] * d[3];
        }
#pragma unroll
    for (int off = 1; off <= 2; off <<= 1) {
        ssq[0][0] += __shfl_xor_sync(0xFFFFFFFFu, ssq[0][0], off);
        ssq[0][1] += __shfl_xor_sync(0xFFFFFFFFu, ssq[0][1], off);
        ssq[1][0] += __shfl_xor_sync(0xFFFFFFFFu, ssq[1][0], off);
        ssq[1][1] += __shfl_xor_sync(0xFFFFFFFFu, ssq[1][1], off);
    }
    float* rp = reinterpret_cast<float*>(smem + SM_RED);   // [4 warps_n][128 rows]
    if (c4 == 0) {
#pragma unroll
        for (int mt = 0; mt < 2; mt++)
#pragma unroll
            for (int h = 0; h < 2; h++)
                rp[wn * BMROWS + wm * 32 + mt * 16 + r4 + 8 * h] = ssq[mt][h];
    }
    __syncthreads();

#pragma unroll
    for (int mt = 0; mt < 2; mt++)
#pragma unroll
        for (int h = 0; h < 2; h++) {
            int rr = wm * 32 + mt * 16 + r4 + 8 * h;
            float s = rp[rr] + rp[BMROWS + rr] + rp[2 * BMROWS + rr] + rp[3 * BMROWS + rr];
            float invn = 1.0f / fmaxf(sqrtf(s), 1e-12f);
            int row = node0 + rr;
            if (row < N_NODES) {
#pragma unroll
                for (int nt = 0; nt < 8; nt++) {
                    float* d = acc[mt][nt];
                    float2 o;
                    o.x = d[2 * h]     * invn;
                    o.y = d[2 * h + 1] * invn;
                    *reinterpret_cast<float2*>(out + (size_t)row * C_OUT + wn * 64 + nt * 8 + 2 * c4) = o;
                }
            }
        }
}

// ---------------- launch ------------------------------------------------------
extern "C" void kernel_launch(void* const* d_in, const int* in_sizes, int n_in,
                              void* d_out, int out_size) {
    const float*     x    = (const float*)d_in[0];      // [100000,128]
    const long long* ei   = (const long long*)d_in[1];  // [2,600000]
    const float*     W    = (const float*)d_in[2];      // [256,256]
    const float*     bias = (const float*)d_in[3];      // [1,256]
    float*           out  = (float*)d_out;              // [100000,256]

    init_kernel<<<ZBLKS + 256, 256>>>(W, ei);

    {
        long long threads = (long long)(E_EDGES / EPW) * 32;
        scatter_kernel<<<(int)((threads + 255) / 256), 256>>>(x, ei);
    }

    {
        cudaFuncSetAttribute(gemm_hmma_kernel, cudaFuncAttributeMaxDynamicSharedMemorySize, SM_TOT);
        int grid = (N_NODES + BMROWS - 1) / BMROWS;     // 782
        gemm_hmma_kernel<<<grid, 512, SM_TOT>>>(x, bias, out);
    }
}